// round 2
// baseline (speedup 1.0000x reference)
#include <cuda_runtime.h>

#define NN 50000
#define NE 800000
#define HCD 64

// ---------------- scratch (static device globals; allocation-free) ----------
__device__ __align__(16) float g_xs[NN * HCD];      // xs of current layer
__device__ __align__(16) float g_h1[NN * HCD];      // relu(layer1 out)
__device__ __align__(16) float g_acc[NN * HCD];     // message accumulator
__device__ __align__(16) float g_asrc[NN * 4];      // per-node a_src (4 heads)
__device__ __align__(16) float g_adst[NN * 4];      // per-node a_dst
__device__ __align__(16) float g_segsum[NN * 4];    // softmax denominators
__device__ __align__(16) float g_walpha[NE * 4];    // exp(leaky(alpha)) per edge/head
__device__ __align__(16) float g_pool[64 * HCD];
__device__ float g_cnt[64];
__device__ __align__(16) float g_ce[8];             // [0..3] layer1, [4..7] layer2

// ---------------- helpers ----------------------------------------------------
__device__ __forceinline__ void red4(float* p, float a, float b, float c, float d) {
#if __CUDA_ARCH__ >= 900
    asm volatile("red.global.add.v4.f32 [%0], {%1,%2,%3,%4};"
                 :: "l"(p), "f"(a), "f"(b), "f"(c), "f"(d) : "memory");
#else
    atomicAdd(p + 0, a); atomicAdd(p + 1, b);
    atomicAdd(p + 2, c); atomicAdd(p + 3, d);
#endif
}

__device__ __forceinline__ float red16(float v) {
    v += __shfl_xor_sync(0xffffffffu, v, 8);
    v += __shfl_xor_sync(0xffffffffu, v, 4);
    v += __shfl_xor_sync(0xffffffffu, v, 2);
    v += __shfl_xor_sync(0xffffffffu, v, 1);
    return v;
}

// ---------------- kernels ----------------------------------------------------
__global__ void k_zero() {
    int i = blockIdx.x * blockDim.x + threadIdx.x;
    if (i < NN * HCD) g_acc[i] = 0.f;
    if (i < NN * 4)   g_segsum[i] = 0.f;
    if (i < 64 * HCD) g_pool[i] = 0.f;
    if (i < 64)       g_cnt[i] = 0.f;
}

// ce[h] = sum_c We[0, h*16+c] * ae[h, c], for both layers.
__global__ void k_ce(const float* __restrict__ We1, const float* __restrict__ ae1,
                     const float* __restrict__ We2, const float* __restrict__ ae2) {
    int t = threadIdx.x;          // 0..127
    int layer = t >> 6;
    int c = t & 63;
    const float* We = layer ? We2 : We1;
    const float* ae = layer ? ae2 : ae1;
    float v = red16(We[c] * ae[c]);
    if ((c & 15) == 0) g_ce[layer * 4 + (c >> 4)] = v;
}

// xs = X @ W  (X:[N,D], W:[D,64]);  fused a_src/a_dst head-dot reductions.
// 512 threads = 8 nodes x 64 out-channels, grid-stride over node tiles.
template<int D>
__global__ void k_linear(const float* __restrict__ Xext,
                         const float* __restrict__ W,
                         const float* __restrict__ as_,
                         const float* __restrict__ ad_) {
    __shared__ float Wsh[D * 64];
    __shared__ float Xsh[8 * D];
    const float* X = Xext ? Xext : g_h1;
    int tid = threadIdx.x;
    for (int i = tid; i < D * 64; i += 512) Wsh[i] = W[i];
    int nl = tid >> 6, c = tid & 63;
    float asv = as_[c], adv = ad_[c];
    int ntiles = (NN + 7) >> 3;
    for (int tile = blockIdx.x; tile < ntiles; tile += gridDim.x) {
        __syncthreads();
        for (int i = tid; i < 8 * D; i += 512) {
            int n = tile * 8 + i / D;
            Xsh[i] = (n < NN) ? X[n * D + (i % D)] : 0.f;
        }
        __syncthreads();
        float sum = 0.f;
        const float* xr = &Xsh[nl * D];
#pragma unroll 16
        for (int k = 0; k < D; k++)
            sum = fmaf(xr[k], Wsh[k * 64 + c], sum);
        int node = tile * 8 + nl;
        if (node < NN) g_xs[node * HCD + c] = sum;
        float ps = red16(sum * asv);
        float pd = red16(sum * adv);
        if ((c & 15) == 0 && node < NN) {
            g_asrc[node * 4 + (c >> 4)] = ps;
            g_adst[node * 4 + (c >> 4)] = pd;
        }
    }
}

// Per edge: w = exp(leaky(a_src[src]+a_dst[dst]+ce*ea)); accumulate segsum[dst].
__global__ void k_edge1(const int* __restrict__ ei, const float* __restrict__ ea,
                        int layer) {
    int e = blockIdx.x * blockDim.x + threadIdx.x;
    if (e >= NE) return;
    int src = ei[e], dst = ei[NE + e];
    float4 s  = *(const float4*)&g_asrc[src * 4];
    float4 d  = *(const float4*)&g_adst[dst * 4];
    float4 cf = *(const float4*)&g_ce[layer * 4];
    float a = ea[e];
    float t;
    float4 w;
    t = s.x + d.x + cf.x * a; t = t > 0.f ? t : 0.2f * t; w.x = __expf(t);
    t = s.y + d.y + cf.y * a; t = t > 0.f ? t : 0.2f * t; w.y = __expf(t);
    t = s.z + d.z + cf.z * a; t = t > 0.f ? t : 0.2f * t; w.z = __expf(t);
    t = s.w + d.w + cf.w * a; t = t > 0.f ? t : 0.2f * t; w.w = __expf(t);
    *(float4*)&g_walpha[e * 4] = w;
    red4(&g_segsum[dst * 4], w.x, w.y, w.z, w.w);
}

// Per (edge, head): coef = w/segsum[dst]; acc[dst, head*16..] += xs[src, head*16..]*coef
__global__ void k_edge2(const int* __restrict__ ei) {
    int t = blockIdx.x * blockDim.x + threadIdx.x;
    int e = t >> 2, h = t & 3;
    if (e >= NE) return;
    int src = ei[e], dst = ei[NE + e];
    float w  = g_walpha[e * 4 + h];
    float ss = g_segsum[dst * 4 + h];
    float coef = w / ss;
    const float4* xv = (const float4*)&g_xs[src * HCD + h * 16];
    float* ap = &g_acc[dst * HCD + h * 16];
#pragma unroll
    for (int q = 0; q < 4; q++) {
        float4 v = xv[q];
        red4(ap + q * 4, v.x * coef, v.y * coef, v.z * coef, v.w * coef);
    }
}

__global__ void k_bias_relu(const float* __restrict__ b) {
    int i = blockIdx.x * blockDim.x + threadIdx.x;
    if (i >= NN * HCD) return;
    g_h1[i] = fmaxf(g_acc[i] + b[i & 63], 0.f);
}

__global__ void k_pool(const int* __restrict__ batch, const float* __restrict__ b2) {
    int t = blockIdx.x * blockDim.x + threadIdx.x;
    int n = t >> 4, q = t & 15;
    if (n >= NN) return;
    int g = batch[n];
    float4 v  = *(const float4*)&g_acc[n * HCD + q * 4];
    float4 bv = *(const float4*)&b2[q * 4];
    red4(&g_pool[g * HCD + q * 4], v.x + bv.x, v.y + bv.y, v.z + bv.z, v.w + bv.w);
    if (q == 0) atomicAdd(&g_cnt[g], 1.f);
}

__global__ void k_final(float* __restrict__ out) {
    int i = blockIdx.x * blockDim.x + threadIdx.x;
    if (i >= 64 * HCD) return;
    out[i] = g_pool[i] / fmaxf(g_cnt[i >> 6], 1.f);
}

// ---------------- launch -----------------------------------------------------
extern "C" void kernel_launch(void* const* d_in, const int* in_sizes, int n_in,
                              void* d_out, int out_size) {
    const float* x   = (const float*)d_in[0];
    const int*   ei  = (const int*)  d_in[1];
    const float* ea  = (const float*)d_in[2];
    const int*   bat = (const int*)  d_in[3];
    const float* W1  = (const float*)d_in[4];
    const float* We1 = (const float*)d_in[5];
    const float* as1 = (const float*)d_in[6];
    const float* ad1 = (const float*)d_in[7];
    const float* ae1 = (const float*)d_in[8];
    const float* b1  = (const float*)d_in[9];
    const float* W2  = (const float*)d_in[10];
    const float* We2 = (const float*)d_in[11];
    const float* as2 = (const float*)d_in[12];
    const float* ad2 = (const float*)d_in[13];
    const float* ae2 = (const float*)d_in[14];
    const float* b2  = (const float*)d_in[15];
    float* out = (float*)d_out;

    const int ZB = (NN * HCD + 255) / 256;        // 12500
    const int E1B = (NE + 255) / 256;             // 3125
    const int E2B = (NE * 4 + 255) / 256;         // 12500
    const int PB = (NN * 16 + 255) / 256;         // 3125

    // ---- layer 1 ----
    k_zero<<<ZB, 256>>>();
    k_ce<<<1, 128>>>(We1, ae1, We2, ae2);
    k_linear<128><<<592, 512>>>(x, W1, as1, ad1);
    k_edge1<<<E1B, 256>>>(ei, ea, 0);
    k_edge2<<<E2B, 256>>>(ei);
    k_bias_relu<<<ZB, 256>>>(b1);

    // ---- layer 2 ----
    k_zero<<<ZB, 256>>>();
    k_linear<64><<<592, 512>>>(nullptr, W2, as2, ad2);
    k_edge1<<<E1B, 256>>>(ei, ea, 1);
    k_edge2<<<E2B, 256>>>(ei);

    // ---- pool ----
    k_pool<<<PB, 256>>>(bat, b2);
    k_final<<<16, 256>>>(out);
}

// round 3
// speedup vs baseline: 1.3086x; 1.3086x over previous
#include <cuda_runtime.h>

#define NN 50000
#define NE 800000
#define HCD 64

// ---------------- scratch (static device globals; allocation-free) ----------
__device__ __align__(16) float g_xs[NN * HCD];      // xs of current layer
__device__ __align__(16) float g_h1[NN * HCD];      // relu(layer1 out)
__device__ __align__(16) float g_acc[NN * HCD];     // layer2 out (pre-pool)
__device__ __align__(16) float g_asrc[NN * 4];      // per-node a_src (4 heads)
__device__ __align__(16) float g_adst[NN * 4];      // per-node a_dst
__device__ __align__(16) float g_walpha[NE * 4];    // exp(leaky(alpha)) per edge/head (CSR order)
__device__ __align__(16) float g_ce[8];             // [0..3] layer1, [4..7] layer2
// CSR build
__device__ int g_deg[NN];
__device__ int g_start[NN + 1];
__device__ int g_cursor[NN];
__device__ __align__(16) int   g_src_sorted[NE];
__device__ __align__(16) float g_ea_sorted[NE];

// ---------------- helpers ----------------------------------------------------
__device__ __forceinline__ float red16(float v) {
    v += __shfl_xor_sync(0xffffffffu, v, 8);
    v += __shfl_xor_sync(0xffffffffu, v, 4);
    v += __shfl_xor_sync(0xffffffffu, v, 2);
    v += __shfl_xor_sync(0xffffffffu, v, 1);
    return v;
}
__device__ __forceinline__ float wred32(float v) {
#pragma unroll
    for (int d = 16; d; d >>= 1) v += __shfl_xor_sync(0xffffffffu, v, d);
    return v;
}

// ---------------- CSR build --------------------------------------------------
__global__ void k_zero_deg() {
    int i = blockIdx.x * blockDim.x + threadIdx.x;
    if (i < NN) g_deg[i] = 0;
}

__global__ void k_hist(const int* __restrict__ ei) {
    int e = blockIdx.x * blockDim.x + threadIdx.x;
    if (e >= NE) return;
    atomicAdd(&g_deg[ei[NE + e]], 1);
}

// single-block exclusive scan over g_deg -> g_start, g_cursor
__global__ void k_scan() {
    __shared__ int wsum[32];
    __shared__ int sbase;
    int tid = threadIdx.x, lane = tid & 31, w = tid >> 5;
    if (tid == 0) sbase = 0;
    __syncthreads();
    for (int base = 0; base < NN; base += 1024) {
        int i = base + tid;
        int v = (i < NN) ? g_deg[i] : 0;
        int x = v;
#pragma unroll
        for (int d = 1; d < 32; d <<= 1) {
            int y = __shfl_up_sync(0xffffffffu, x, d);
            if (lane >= d) x += y;
        }
        if (lane == 31) wsum[w] = x;
        __syncthreads();
        if (w == 0) {
            int t = wsum[lane];
#pragma unroll
            for (int d = 1; d < 32; d <<= 1) {
                int y = __shfl_up_sync(0xffffffffu, t, d);
                if (lane >= d) t += y;
            }
            wsum[lane] = t;
        }
        __syncthreads();
        int excl = sbase + (w ? wsum[w - 1] : 0) + x - v;
        if (i < NN) { g_start[i] = excl; g_cursor[i] = excl; }
        __syncthreads();
        if (tid == 0) sbase += wsum[31];
        __syncthreads();
    }
    if (threadIdx.x == 0) g_start[NN] = sbase;
}

__global__ void k_scatter(const int* __restrict__ ei, const float* __restrict__ ea) {
    int e = blockIdx.x * blockDim.x + threadIdx.x;
    if (e >= NE) return;
    int dst = ei[NE + e];
    int pos = atomicAdd(&g_cursor[dst], 1);
    g_src_sorted[pos] = ei[e];
    g_ea_sorted[pos]  = ea[e];
}

// ---------------- params -----------------------------------------------------
// ce[h] = sum_c We[0, h*16+c] * ae[h, c], for both layers.
__global__ void k_ce(const float* __restrict__ We1, const float* __restrict__ ae1,
                     const float* __restrict__ We2, const float* __restrict__ ae2) {
    int t = threadIdx.x;          // 0..127
    int layer = t >> 6;
    int c = t & 63;
    const float* We = layer ? We2 : We1;
    const float* ae = layer ? ae2 : ae1;
    float v = red16(We[c] * ae[c]);
    if ((c & 15) == 0) g_ce[layer * 4 + (c >> 4)] = v;
}

// ---------------- linear -----------------------------------------------------
// xs = X @ W  (X:[N,D], W:[D,64]); fused a_src/a_dst head-dot reductions.
template<int D>
__global__ void k_linear(const float* __restrict__ Xext,
                         const float* __restrict__ W,
                         const float* __restrict__ as_,
                         const float* __restrict__ ad_) {
    __shared__ float Wsh[D * 64];
    __shared__ float Xsh[8 * D];
    const float* X = Xext ? Xext : g_h1;
    int tid = threadIdx.x;
    for (int i = tid; i < D * 64; i += 512) Wsh[i] = W[i];
    int nl = tid >> 6, c = tid & 63;
    float asv = as_[c], adv = ad_[c];
    int ntiles = (NN + 7) >> 3;
    for (int tile = blockIdx.x; tile < ntiles; tile += gridDim.x) {
        __syncthreads();
        for (int i = tid; i < 8 * D; i += 512) {
            int n = tile * 8 + i / D;
            Xsh[i] = (n < NN) ? X[n * D + (i % D)] : 0.f;
        }
        __syncthreads();
        float sum = 0.f;
        const float* xr = &Xsh[nl * D];
#pragma unroll 16
        for (int k = 0; k < D; k++)
            sum = fmaf(xr[k], Wsh[k * 64 + c], sum);
        int node = tile * 8 + nl;
        if (node < NN) g_xs[node * HCD + c] = sum;
        float ps = red16(sum * asv);
        float pd = red16(sum * adv);
        if ((c & 15) == 0 && node < NN) {
            g_asrc[node * 4 + (c >> 4)] = ps;
            g_adst[node * 4 + (c >> 4)] = pd;
        }
    }
}

// ---------------- fused edge aggregation (one warp per dst node) -------------
// pass1: w = exp(leaky(a_src[src]+a_dst[dst]+ce*ea)) per head, warp-sum denom.
// pass2: acc[c] = sum_j w[h(c)] * xs[src_j][c]; out = acc/denom + bias (opt relu).
__global__ void k_edge_fused(int layer, const float* __restrict__ bias,
                             float* __restrict__ out, int relu) {
    int gw = (blockIdx.x * blockDim.x + threadIdx.x) >> 5;
    if (gw >= NN) return;
    int lane = threadIdx.x & 31;
    int s0 = g_start[gw], s1 = g_start[gw + 1];

    float4 ad = *(const float4*)&g_adst[gw * 4];
    float4 cf = *(const float4*)&g_ce[layer * 4];

    float ssx = 0.f, ssy = 0.f, ssz = 0.f, ssw = 0.f;
    for (int j = s0 + lane; j < s1; j += 32) {
        int src = g_src_sorted[j];
        float4 s = *(const float4*)&g_asrc[src * 4];
        float a = g_ea_sorted[j];
        float t; float4 w;
        t = s.x + ad.x + cf.x * a; t = t > 0.f ? t : 0.2f * t; w.x = __expf(t);
        t = s.y + ad.y + cf.y * a; t = t > 0.f ? t : 0.2f * t; w.y = __expf(t);
        t = s.z + ad.z + cf.z * a; t = t > 0.f ? t : 0.2f * t; w.z = __expf(t);
        t = s.w + ad.w + cf.w * a; t = t > 0.f ? t : 0.2f * t; w.w = __expf(t);
        *(float4*)&g_walpha[j * 4] = w;
        ssx += w.x; ssy += w.y; ssz += w.z; ssw += w.w;
    }
    ssx = wred32(ssx); ssy = wred32(ssy); ssz = wred32(ssz); ssw = wred32(ssw);
    __syncwarp();   // order pass1 w-stores before pass2 loads across lanes

    int c = lane * 2;          // two consecutive channels, same head
    int h = c >> 4;
    float denom = (h == 0) ? ssx : (h == 1) ? ssy : (h == 2) ? ssz : ssw;
    float rcp = (denom > 0.f) ? (1.f / denom) : 0.f;

    float acc0 = 0.f, acc1 = 0.f;
#pragma unroll 4
    for (int j = s0; j < s1; ++j) {
        int src = g_src_sorted[j];                         // broadcast load
        float w = g_walpha[j * 4 + h];
        float2 xv = *(const float2*)&g_xs[src * HCD + c];
        acc0 = fmaf(w, xv.x, acc0);
        acc1 = fmaf(w, xv.y, acc1);
    }
    float o0 = acc0 * rcp + bias[c];
    float o1 = acc1 * rcp + bias[c + 1];
    if (relu) { o0 = fmaxf(o0, 0.f); o1 = fmaxf(o1, 0.f); }
    float2 ov; ov.x = o0; ov.y = o1;
    *(float2*)&out[gw * HCD + c] = ov;
}

// ---------------- pool (batch is sorted -> segment mean per graph) -----------
__device__ __forceinline__ int lowerb(const int* a, int n, int key) {
    int lo = 0, hi = n;
    while (lo < hi) { int m = (lo + hi) >> 1; if (a[m] < key) lo = m + 1; else hi = m; }
    return lo;
}

__global__ void k_pool(const int* __restrict__ batch, float* __restrict__ out) {
    int g = blockIdx.x;
    int lo = lowerb(batch, NN, g);
    int hi = lowerb(batch, NN, g + 1);
    int tid = threadIdx.x;             // 256
    int c = tid & 63, s = tid >> 6;    // 4 slices
    float acc = 0.f;
    for (int n = lo + s; n < hi; n += 4) acc += g_acc[n * HCD + c];
    __shared__ float sh[256];
    sh[tid] = acc;
    __syncthreads();
    if (s == 0) {
        float v = sh[c] + sh[c + 64] + sh[c + 128] + sh[c + 192];
        float cnt = (float)(hi - lo);
        out[g * HCD + c] = v / fmaxf(cnt, 1.f);
    }
}

// ---------------- launch -----------------------------------------------------
extern "C" void kernel_launch(void* const* d_in, const int* in_sizes, int n_in,
                              void* d_out, int out_size) {
    const float* x   = (const float*)d_in[0];
    const int*   ei  = (const int*)  d_in[1];
    const float* ea  = (const float*)d_in[2];
    const int*   bat = (const int*)  d_in[3];
    const float* W1  = (const float*)d_in[4];
    const float* We1 = (const float*)d_in[5];
    const float* as1 = (const float*)d_in[6];
    const float* ad1 = (const float*)d_in[7];
    const float* ae1 = (const float*)d_in[8];
    const float* b1  = (const float*)d_in[9];
    const float* W2  = (const float*)d_in[10];
    const float* We2 = (const float*)d_in[11];
    const float* as2 = (const float*)d_in[12];
    const float* ad2 = (const float*)d_in[13];
    const float* ae2 = (const float*)d_in[14];
    const float* b2  = (const float*)d_in[15];
    float* out = (float*)d_out;

    const int EB = (NE + 255) / 256;               // 3125
    const int NB = (NN + 255) / 256;               // 196
    const int FB = (NN * 32 + 255) / 256;          // 6250 (one warp per node)

    // Pointers to device globals (host side).
    float *p_h1, *p_acc;
    cudaGetSymbolAddress((void**)&p_h1,  g_h1);
    cudaGetSymbolAddress((void**)&p_acc, g_acc);

    // ---- CSR build (graph static across layers) ----
    k_zero_deg<<<NB, 256>>>();
    k_hist<<<EB, 256>>>(ei);
    k_scan<<<1, 1024>>>();
    k_scatter<<<EB, 256>>>(ei, ea);
    k_ce<<<1, 128>>>(We1, ae1, We2, ae2);

    // ---- layer 1 ----
    k_linear<128><<<592, 512>>>(x, W1, as1, ad1);
    k_edge_fused<<<FB, 256>>>(0, b1, p_h1, 1);

    // ---- layer 2 ----
    k_linear<64><<<592, 512>>>(nullptr, W2, as2, ad2);
    k_edge_fused<<<FB, 256>>>(1, b2, p_acc, 0);

    // ---- pool ----
    k_pool<<<64, 256>>>(bat, out);
}

// round 6
// speedup vs baseline: 1.8255x; 1.3951x over previous
#include <cuda_runtime.h>

#define NN 50000
#define NE 800000
#define HCD 64
#define NTILES 49   // ceil(50000/1024)

// ---------------- scratch (static device globals; allocation-free) ----------
__device__ __align__(16) float g_xs[NN * HCD];      // xs of current layer
__device__ __align__(16) float g_h1[NN * HCD];      // relu(layer1 out)
__device__ __align__(16) float g_acc[NN * HCD];     // layer2 out (pre-pool)
__device__ __align__(16) float g_asrc[NN * 4];      // per-node a_src (4 heads)
__device__ __align__(16) float g_adst[NN * 4];      // per-node a_dst
__device__ __align__(16) float g_walpha[NE * 4];    // exp(leaky(alpha)) per edge/head (CSR order)
__device__ __align__(16) float g_ce[8];             // [0..3] layer1, [4..7] layer2
// CSR build
__device__ int g_deg[NN];
__device__ int g_start[NN + 1];
__device__ int g_cursor[NN];
__device__ int g_bsum[NTILES];
__device__ int g_boff[NTILES];
__device__ __align__(16) int2 g_edge[NE];           // {src, ea bits} in CSR order

// ---------------- helpers ----------------------------------------------------
__device__ __forceinline__ float red16(float v) {
    v += __shfl_xor_sync(0xffffffffu, v, 8);
    v += __shfl_xor_sync(0xffffffffu, v, 4);
    v += __shfl_xor_sync(0xffffffffu, v, 2);
    v += __shfl_xor_sync(0xffffffffu, v, 1);
    return v;
}
__device__ __forceinline__ float wred32(float v) {
#pragma unroll
    for (int d = 16; d; d >>= 1) v += __shfl_xor_sync(0xffffffffu, v, d);
    return v;
}

// ---------------- init: zero deg + ce constants ------------------------------
__global__ void k_init(const float* __restrict__ We1, const float* __restrict__ ae1,
                       const float* __restrict__ We2, const float* __restrict__ ae2) {
    int i = blockIdx.x * blockDim.x + threadIdx.x;
    if (i < NN) g_deg[i] = 0;
    if (blockIdx.x == 0 && threadIdx.x < 128) {
        int t = threadIdx.x;
        int layer = t >> 6;
        int c = t & 63;
        const float* We = layer ? We2 : We1;
        const float* ae = layer ? ae2 : ae1;
        float v = red16(We[c] * ae[c]);
        if ((c & 15) == 0) g_ce[layer * 4 + (c >> 4)] = v;
    }
}

__global__ void k_hist(const int* __restrict__ ei) {
    int e = blockIdx.x * blockDim.x + threadIdx.x;
    if (e >= NE) return;
    atomicAdd(&g_deg[ei[NE + e]], 1);
}

// ---------------- multi-block scan -------------------------------------------
__global__ void k_scanA() {           // per-tile reduction
    __shared__ int wsum[32];
    int b = blockIdx.x, tid = threadIdx.x, lane = tid & 31, w = tid >> 5;
    int i = b * 1024 + tid;
    int v = (i < NN) ? g_deg[i] : 0;
#pragma unroll
    for (int d = 16; d; d >>= 1) v += __shfl_xor_sync(0xffffffffu, v, d);
    if (lane == 0) wsum[w] = v;
    __syncthreads();
    if (w == 0) {
        int t = wsum[lane];
#pragma unroll
        for (int d = 16; d; d >>= 1) t += __shfl_xor_sync(0xffffffffu, t, d);
        if (lane == 0) g_bsum[b] = t;
    }
}

__global__ void k_scanB() {           // scan 49 tile sums (64 threads)
    __shared__ int ws[2];
    int tid = threadIdx.x, lane = tid & 31, w = tid >> 5;
    int v = (tid < NTILES) ? g_bsum[tid] : 0;
    int x = v;
#pragma unroll
    for (int d = 1; d < 32; d <<= 1) {
        int y = __shfl_up_sync(0xffffffffu, x, d);
        if (lane >= d) x += y;
    }
    if (lane == 31) ws[w] = x;
    __syncthreads();
    if (w == 1) x += ws[0];
    if (tid < NTILES) g_boff[tid] = x - v;
    if (tid == NTILES - 1) g_start[NN] = x;
}

__global__ void k_scanC() {           // per-tile scan + global offset
    __shared__ int wsum[32];
    int b = blockIdx.x, tid = threadIdx.x, lane = tid & 31, w = tid >> 5;
    int i = b * 1024 + tid;
    int v = (i < NN) ? g_deg[i] : 0;
    int x = v;
#pragma unroll
    for (int d = 1; d < 32; d <<= 1) {
        int y = __shfl_up_sync(0xffffffffu, x, d);
        if (lane >= d) x += y;
    }
    if (lane == 31) wsum[w] = x;
    __syncthreads();
    if (w == 0) {
        int t = wsum[lane];
#pragma unroll
        for (int d = 1; d < 32; d <<= 1) {
            int y = __shfl_up_sync(0xffffffffu, t, d);
            if (lane >= d) t += y;
        }
        wsum[lane] = t;
    }
    __syncthreads();
    int excl = g_boff[b] + (w ? wsum[w - 1] : 0) + x - v;
    if (i < NN) { g_start[i] = excl; g_cursor[i] = excl; }
}

__global__ void k_scatter(const int* __restrict__ ei, const float* __restrict__ ea) {
    int e = blockIdx.x * blockDim.x + threadIdx.x;
    if (e >= NE) return;
    int dst = ei[NE + e];
    int pos = atomicAdd(&g_cursor[dst], 1);
    g_edge[pos] = make_int2(ei[e], __float_as_int(ea[e]));
}

// ---------------- register-blocked linear ------------------------------------
// xs = X @ W  (X:[N,D], W:[D,64]); fused a_src/a_dst head-dot reductions.
// Block tile: 128 nodes x 64 cols; 256 threads, each 4 nodes x 8 cols.
// Thread: cg = tid&7 -> cols 8cg..8cg+7 (single head h=cg>>1); ng = tid>>3 -> nodes 4ng..
template<int D>
__global__ void __launch_bounds__(256) k_linear(const float* __restrict__ Xext,
                                                const float* __restrict__ W,
                                                const float* __restrict__ as_,
                                                const float* __restrict__ ad_) {
    __shared__ float Wsh[D * 64];
    __shared__ float Xsh[128 * D];
    const float* X = Xext ? Xext : g_h1;
    int tid = threadIdx.x;
    int cg = tid & 7, ng = tid >> 3;
    int c0 = cg * 8;
    int h = cg >> 1;

    for (int i = tid * 4; i < D * 64; i += 1024)
        *(float4*)&Wsh[i] = *(const float4*)&W[i];

    int n0 = blockIdx.x * 128;
    int cnt = NN - n0; if (cnt > 128) cnt = 128;
    for (int i = tid * 4; i < cnt * D; i += 1024)
        *(float4*)&Xsh[i] = *(const float4*)&X[n0 * D + i];
    __syncthreads();

    float acc[4][8];
#pragma unroll
    for (int i = 0; i < 4; i++)
#pragma unroll
        for (int j = 0; j < 8; j++) acc[i][j] = 0.f;

#pragma unroll 2
    for (int k = 0; k < D; k++) {
        float4 wlo = *(const float4*)&Wsh[k * 64 + c0];
        float4 whi = *(const float4*)&Wsh[k * 64 + c0 + 4];
        float wr[8] = {wlo.x, wlo.y, wlo.z, wlo.w, whi.x, whi.y, whi.z, whi.w};
#pragma unroll
        for (int i = 0; i < 4; i++) {
            float xv = Xsh[(ng * 4 + i) * D + k];
#pragma unroll
            for (int j = 0; j < 8; j++)
                acc[i][j] = fmaf(xv, wr[j], acc[i][j]);
        }
    }

    // attention dot weights for this thread's columns
    float asv[8], adv[8];
#pragma unroll
    for (int j = 0; j < 8; j++) { asv[j] = as_[c0 + j]; adv[j] = ad_[c0 + j]; }

#pragma unroll
    for (int i = 0; i < 4; i++) {
        int node = n0 + ng * 4 + i;
        float ps = 0.f, pd = 0.f;
#pragma unroll
        for (int j = 0; j < 8; j++) {
            ps = fmaf(acc[i][j], asv[j], ps);
            pd = fmaf(acc[i][j], adv[j], pd);
        }
        ps += __shfl_xor_sync(0xffffffffu, ps, 1);   // combine cg pair -> full head dot
        pd += __shfl_xor_sync(0xffffffffu, pd, 1);
        if (node < NN) {
            float4 lo = make_float4(acc[i][0], acc[i][1], acc[i][2], acc[i][3]);
            float4 hi = make_float4(acc[i][4], acc[i][5], acc[i][6], acc[i][7]);
            *(float4*)&g_xs[node * HCD + c0] = lo;
            *(float4*)&g_xs[node * HCD + c0 + 4] = hi;
            if ((cg & 1) == 0) {
                g_asrc[node * 4 + h] = ps;
                g_adst[node * 4 + h] = pd;
            }
        }
    }
}

// ---------------- fused edge aggregation (one warp per dst node) -------------
__global__ void k_edge_fused(int layer, const float* __restrict__ bias,
                             float* __restrict__ out, int relu) {
    int gw = (blockIdx.x * blockDim.x + threadIdx.x) >> 5;
    if (gw >= NN) return;
    int lane = threadIdx.x & 31;
    int s0 = g_start[gw], s1 = g_start[gw + 1];

    float4 ad = *(const float4*)&g_adst[gw * 4];
    float4 cf = *(const float4*)&g_ce[layer * 4];

    float ssx = 0.f, ssy = 0.f, ssz = 0.f, ssw = 0.f;
    for (int j = s0 + lane; j < s1; j += 32) {
        int2 ep = g_edge[j];
        int src = ep.x;
        float a = __int_as_float(ep.y);
        float4 s = *(const float4*)&g_asrc[src * 4];
        float t; float4 w;
        t = s.x + ad.x + cf.x * a; t = t > 0.f ? t : 0.2f * t; w.x = __expf(t);
        t = s.y + ad.y + cf.y * a; t = t > 0.f ? t : 0.2f * t; w.y = __expf(t);
        t = s.z + ad.z + cf.z * a; t = t > 0.f ? t : 0.2f * t; w.z = __expf(t);
        t = s.w + ad.w + cf.w * a; t = t > 0.f ? t : 0.2f * t; w.w = __expf(t);
        *(float4*)&g_walpha[j * 4] = w;
        ssx += w.x; ssy += w.y; ssz += w.z; ssw += w.w;
    }
    ssx = wred32(ssx); ssy = wred32(ssy); ssz = wred32(ssz); ssw = wred32(ssw);
    __syncwarp();   // order pass1 w-stores before pass2 loads across lanes

    int c = lane * 2;          // two consecutive channels, same head
    int h = lane >> 3;
    float denom = (h == 0) ? ssx : (h == 1) ? ssy : (h == 2) ? ssz : ssw;
    float rcp = (denom > 0.f) ? (1.f / denom) : 0.f;

    float acc0 = 0.f, acc1 = 0.f;
#pragma unroll 4
    for (int j = s0; j < s1; ++j) {
        int src = g_edge[j].x;                         // broadcast load
        float w = g_walpha[j * 4 + h];
        float2 xv = *(const float2*)&g_xs[src * HCD + c];
        acc0 = fmaf(w, xv.x, acc0);
        acc1 = fmaf(w, xv.y, acc1);
    }
    float o0 = acc0 * rcp + bias[c];
    float o1 = acc1 * rcp + bias[c + 1];
    if (relu) { o0 = fmaxf(o0, 0.f); o1 = fmaxf(o1, 0.f); }
    float2 ov; ov.x = o0; ov.y = o1;
    *(float2*)&out[gw * HCD + c] = ov;
}

// ---------------- pool (batch is sorted -> segment mean per graph) -----------
__device__ __forceinline__ int lowerb(const int* a, int n, int key) {
    int lo = 0, hi = n;
    while (lo < hi) { int m = (lo + hi) >> 1; if (a[m] < key) lo = m + 1; else hi = m; }
    return lo;
}

__global__ void k_pool(const int* __restrict__ batch, float* __restrict__ out) {
    int g = blockIdx.x;
    int lo = lowerb(batch, NN, g);
    int hi = lowerb(batch, NN, g + 1);
    int tid = threadIdx.x;             // 256
    int c = tid & 63, s = tid >> 6;    // 4 slices
    float acc = 0.f;
    for (int n = lo + s; n < hi; n += 4) acc += g_acc[n * HCD + c];
    __shared__ float sh[256];
    sh[tid] = acc;
    __syncthreads();
    if (s == 0) {
        float v = sh[c] + sh[c + 64] + sh[c + 128] + sh[c + 192];
        float cnt = (float)(hi - lo);
        out[g * HCD + c] = v / fmaxf(cnt, 1.f);
    }
}

// ---------------- launch -----------------------------------------------------
extern "C" void kernel_launch(void* const* d_in, const int* in_sizes, int n_in,
                              void* d_out, int out_size) {
    const float* x   = (const float*)d_in[0];
    const int*   ei  = (const int*)  d_in[1];
    const float* ea  = (const float*)d_in[2];
    const int*   bat = (const int*)  d_in[3];
    const float* W1  = (const float*)d_in[4];
    const float* We1 = (const float*)d_in[5];
    const float* as1 = (const float*)d_in[6];
    const float* ad1 = (const float*)d_in[7];
    const float* ae1 = (const float*)d_in[8];
    const float* b1  = (const float*)d_in[9];
    const float* W2  = (const float*)d_in[10];
    const float* We2 = (const float*)d_in[11];
    const float* as2 = (const float*)d_in[12];
    const float* ad2 = (const float*)d_in[13];
    const float* ae2 = (const float*)d_in[14];
    const float* b2  = (const float*)d_in[15];
    float* out = (float*)d_out;

    const int EB = (NE + 255) / 256;               // 3125
    const int NB = (NN + 255) / 256;               // 196
    const int FB = (NN * 32 + 255) / 256;          // 6250 (one warp per node)
    const int LB = (NN + 127) / 128;               // 391 linear tiles

    float *p_h1, *p_acc;
    cudaGetSymbolAddress((void**)&p_h1,  g_h1);
    cudaGetSymbolAddress((void**)&p_acc, g_acc);

    // ---- CSR build (graph static across layers) ----
    k_init<<<NB, 256>>>(We1, ae1, We2, ae2);
    k_hist<<<EB, 256>>>(ei);
    k_scanA<<<NTILES, 1024>>>();
    k_scanB<<<1, 64>>>();
    k_scanC<<<NTILES, 1024>>>();
    k_scatter<<<EB, 256>>>(ei, ea);

    // ---- layer 1 ----
    k_linear<128><<<LB, 256>>>(x, W1, as1, ad1);
    k_edge_fused<<<FB, 256>>>(0, b1, p_h1, 1);

    // ---- layer 2 ----
    k_linear<64><<<LB, 256>>>(nullptr, W2, as2, ad2);
    k_edge_fused<<<FB, 256>>>(1, b2, p_acc, 0);

    // ---- pool ----
    k_pool<<<64, 256>>>(bat, out);
}

// round 8
// speedup vs baseline: 1.8448x; 1.0106x over previous
#include <cuda_runtime.h>

#define NN 50000
#define NE 800000
#define HCD 64
#define NTILES 49   // ceil(50000/1024)

// ---------------- scratch (static device globals; allocation-free) ----------
__device__ __align__(16) float g_xs[NN * HCD];      // xs of current layer
__device__ __align__(16) float g_h1[NN * HCD];      // relu(layer1 out)
__device__ __align__(16) float g_acc[NN * HCD];     // layer2 out (pre-pool)
__device__ __align__(16) float g_asrc[NN * 4];      // per-node a_src (4 heads)
__device__ __align__(16) float g_adst[NN * 4];      // per-node a_dst
__device__ __align__(16) float g_ce[8];             // [0..3] layer1, [4..7] layer2
// CSR build
__device__ int g_deg[NN];
__device__ int g_start[NN + 1];
__device__ int g_cursor[NN];
__device__ int g_bsum[NTILES];
__device__ __align__(16) int2 g_edge[NE];           // {src, ea bits} in CSR order

// ---------------- helpers ----------------------------------------------------
__device__ __forceinline__ float red16(float v) {
    v += __shfl_xor_sync(0xffffffffu, v, 8);
    v += __shfl_xor_sync(0xffffffffu, v, 4);
    v += __shfl_xor_sync(0xffffffffu, v, 2);
    v += __shfl_xor_sync(0xffffffffu, v, 1);
    return v;
}

// ---------------- init: zero deg + ce constants ------------------------------
__global__ void k_init(const float* __restrict__ We1, const float* __restrict__ ae1,
                       const float* __restrict__ We2, const float* __restrict__ ae2) {
    int i = blockIdx.x * blockDim.x + threadIdx.x;
    if (i < NN) g_deg[i] = 0;
    if (blockIdx.x == 0 && threadIdx.x < 128) {
        int t = threadIdx.x;
        int layer = t >> 6;
        int c = t & 63;
        const float* We = layer ? We2 : We1;
        const float* ae = layer ? ae2 : ae1;
        float v = red16(We[c] * ae[c]);
        if ((c & 15) == 0) g_ce[layer * 4 + (c >> 4)] = v;
    }
}

// 4 edges per thread, int4 loads for MLP. (NE % 4 == 0, so no partial quads.)
__global__ void k_hist(const int* __restrict__ ei) {
    int t = blockIdx.x * blockDim.x + threadIdx.x;
    int e = t * 4;
    if (e >= NE) return;
    int4 d = *(const int4*)&ei[NE + e];
    atomicAdd(&g_deg[d.x], 1);
    atomicAdd(&g_deg[d.y], 1);
    atomicAdd(&g_deg[d.z], 1);
    atomicAdd(&g_deg[d.w], 1);
}

// ---------------- scan -------------------------------------------------------
__global__ void k_scanA() {           // per-tile reduction
    __shared__ int wsum[32];
    int b = blockIdx.x, tid = threadIdx.x, lane = tid & 31, w = tid >> 5;
    int i = b * 1024 + tid;
    int v = (i < NN) ? g_deg[i] : 0;
#pragma unroll
    for (int d = 16; d; d >>= 1) v += __shfl_xor_sync(0xffffffffu, v, d);
    if (lane == 0) wsum[w] = v;
    __syncthreads();
    if (w == 0) {
        int t = wsum[lane];
#pragma unroll
        for (int d = 16; d; d >>= 1) t += __shfl_xor_sync(0xffffffffu, t, d);
        if (lane == 0) g_bsum[b] = t;
    }
}

// per-tile scan + (redundant) scan of tile sums for the global offset.
// NOTE: cross-warp handoff of ws2[0] uses BLOCK-level barriers (round-7 bug
// was a __syncwarp here -> race on uninitialized smem -> OOB scatter).
__global__ void k_scanC() {
    __shared__ int wsum[32];
    __shared__ int sboff;
    __shared__ int ws2[2];
    int b = blockIdx.x, tid = threadIdx.x, lane = tid & 31, w = tid >> 5;

    // --- scan the NTILES tile sums with threads 0..63 ---
    int v2 = 0, x2 = 0;
    if (tid < 64) {
        v2 = (tid < NTILES) ? g_bsum[tid] : 0;
        x2 = v2;
#pragma unroll
        for (int d = 1; d < 32; d <<= 1) {
            int y = __shfl_up_sync(0xffffffffu, x2, d);
            if (lane >= d) x2 += y;
        }
        if (lane == 31) ws2[w] = x2;
    }
    __syncthreads();                       // publish ws2[0] to warp 1
    if (tid >= 32 && tid < 64) x2 += ws2[0];
    if (tid == b) sboff = x2 - v2;         // exclusive offset of this tile
    if (b == 0 && tid == NTILES - 1) g_start[NN] = x2;
    __syncthreads();                       // publish sboff

    // --- per-tile scan of g_deg ---
    int i = b * 1024 + tid;
    int v = (i < NN) ? g_deg[i] : 0;
    int x = v;
#pragma unroll
    for (int d = 1; d < 32; d <<= 1) {
        int y = __shfl_up_sync(0xffffffffu, x, d);
        if (lane >= d) x += y;
    }
    if (lane == 31) wsum[w] = x;
    __syncthreads();
    if (w == 0) {
        int t = wsum[lane];
#pragma unroll
        for (int d = 1; d < 32; d <<= 1) {
            int y = __shfl_up_sync(0xffffffffu, t, d);
            if (lane >= d) t += y;
        }
        wsum[lane] = t;
    }
    __syncthreads();
    int excl = sboff + (w ? wsum[w - 1] : 0) + x - v;
    if (i < NN) { g_start[i] = excl; g_cursor[i] = excl; }
}

// 4 edges per thread, vector loads for MLP.
__global__ void k_scatter(const int* __restrict__ ei, const float* __restrict__ ea) {
    int t = blockIdx.x * blockDim.x + threadIdx.x;
    int e = t * 4;
    if (e >= NE) return;
    int4   s4 = *(const int4*)&ei[e];
    int4   d4 = *(const int4*)&ei[NE + e];
    float4 a4 = *(const float4*)&ea[e];
    int p;
    p = atomicAdd(&g_cursor[d4.x], 1); g_edge[p] = make_int2(s4.x, __float_as_int(a4.x));
    p = atomicAdd(&g_cursor[d4.y], 1); g_edge[p] = make_int2(s4.y, __float_as_int(a4.y));
    p = atomicAdd(&g_cursor[d4.z], 1); g_edge[p] = make_int2(s4.z, __float_as_int(a4.z));
    p = atomicAdd(&g_cursor[d4.w], 1); g_edge[p] = make_int2(s4.w, __float_as_int(a4.w));
}

// ---------------- register-blocked linear ------------------------------------
// xs = X @ W  (X:[N,D], W:[D,64]); fused a_src/a_dst head-dot reductions.
template<int D>
__global__ void __launch_bounds__(256) k_linear(const float* __restrict__ Xext,
                                                const float* __restrict__ W,
                                                const float* __restrict__ as_,
                                                const float* __restrict__ ad_) {
    __shared__ float Wsh[D * 64];
    __shared__ float Xsh[128 * D];
    const float* X = Xext ? Xext : g_h1;
    int tid = threadIdx.x;
    int cg = tid & 7, ng = tid >> 3;
    int c0 = cg * 8;
    int h = cg >> 1;

    for (int i = tid * 4; i < D * 64; i += 1024)
        *(float4*)&Wsh[i] = *(const float4*)&W[i];

    int n0 = blockIdx.x * 128;
    int cnt = NN - n0; if (cnt > 128) cnt = 128;
    for (int i = tid * 4; i < cnt * D; i += 1024)
        *(float4*)&Xsh[i] = *(const float4*)&X[n0 * D + i];
    __syncthreads();

    float acc[4][8];
#pragma unroll
    for (int i = 0; i < 4; i++)
#pragma unroll
        for (int j = 0; j < 8; j++) acc[i][j] = 0.f;

#pragma unroll 2
    for (int k = 0; k < D; k++) {
        float4 wlo = *(const float4*)&Wsh[k * 64 + c0];
        float4 whi = *(const float4*)&Wsh[k * 64 + c0 + 4];
        float wr[8] = {wlo.x, wlo.y, wlo.z, wlo.w, whi.x, whi.y, whi.z, whi.w};
#pragma unroll
        for (int i = 0; i < 4; i++) {
            float xv = Xsh[(ng * 4 + i) * D + k];
#pragma unroll
            for (int j = 0; j < 8; j++)
                acc[i][j] = fmaf(xv, wr[j], acc[i][j]);
        }
    }

    float asv[8], adv[8];
#pragma unroll
    for (int j = 0; j < 8; j++) { asv[j] = as_[c0 + j]; adv[j] = ad_[c0 + j]; }

#pragma unroll
    for (int i = 0; i < 4; i++) {
        int node = n0 + ng * 4 + i;
        float ps = 0.f, pd = 0.f;
#pragma unroll
        for (int j = 0; j < 8; j++) {
            ps = fmaf(acc[i][j], asv[j], ps);
            pd = fmaf(acc[i][j], adv[j], pd);
        }
        ps += __shfl_xor_sync(0xffffffffu, ps, 1);
        pd += __shfl_xor_sync(0xffffffffu, pd, 1);
        if (node < NN) {
            float4 lo = make_float4(acc[i][0], acc[i][1], acc[i][2], acc[i][3]);
            float4 hi = make_float4(acc[i][4], acc[i][5], acc[i][6], acc[i][7]);
            *(float4*)&g_xs[node * HCD + c0] = lo;
            *(float4*)&g_xs[node * HCD + c0 + 4] = hi;
            if ((cg & 1) == 0) {
                g_asrc[node * 4 + h] = ps;
                g_adst[node * 4 + h] = pd;
            }
        }
    }
}

// ---------------- single-pass fused edge aggregation (one warp per dst) ------
// Softmax normalization is linear: accumulate msg = sum_j w_j*xs[src_j] and
// denom = sum_j w_j in ONE loop; divide at the end. Each lane recomputes its
// own head's w (all lanes of a head group hold the identical full denominator,
// so no reduction is needed).
__global__ void k_edge_fused(int layer, const float* __restrict__ bias,
                             float* __restrict__ out, int relu) {
    int gw = (blockIdx.x * blockDim.x + threadIdx.x) >> 5;
    if (gw >= NN) return;
    int lane = threadIdx.x & 31;
    int c = lane * 2;               // two consecutive channels, same head
    int h = lane >> 3;
    int s0 = g_start[gw], s1 = g_start[gw + 1];

    float adh = g_adst[gw * 4 + h];
    float cfh = g_ce[layer * 4 + h];

    float acc0 = 0.f, acc1 = 0.f, dsum = 0.f;

    if (s0 < s1) {
        int2 ep = g_edge[s0];                         // prefetch (broadcast)
        for (int j = s0; j < s1; ++j) {
            int src = ep.x;
            float a = __int_as_float(ep.y);
            if (j + 1 < s1) ep = g_edge[j + 1];       // next edge in flight
            float sh = g_asrc[src * 4 + h];           // 16B/warp, one sector
            float t = sh + adh + cfh * a;
            t = t > 0.f ? t : 0.2f * t;
            float w = __expf(t);
            dsum += w;
            float2 xv = *(const float2*)&g_xs[src * HCD + c];   // 256B/warp
            acc0 = fmaf(w, xv.x, acc0);
            acc1 = fmaf(w, xv.y, acc1);
        }
    }

    float rcp = (dsum > 0.f) ? (1.f / dsum) : 0.f;
    float2 bv = *(const float2*)&bias[c];
    float o0 = acc0 * rcp + bv.x;
    float o1 = acc1 * rcp + bv.y;
    if (relu) { o0 = fmaxf(o0, 0.f); o1 = fmaxf(o1, 0.f); }
    float2 ov; ov.x = o0; ov.y = o1;
    *(float2*)&out[gw * HCD + c] = ov;
}

// ---------------- pool (batch is sorted -> segment mean per graph) -----------
__device__ __forceinline__ int lowerb(const int* a, int n, int key) {
    int lo = 0, hi = n;
    while (lo < hi) { int m = (lo + hi) >> 1; if (a[m] < key) lo = m + 1; else hi = m; }
    return lo;
}

__global__ void k_pool(const int* __restrict__ batch, float* __restrict__ out) {
    int g = blockIdx.x;
    int lo = lowerb(batch, NN, g);
    int hi = lowerb(batch, NN, g + 1);
    int tid = threadIdx.x;             // 256
    int c = tid & 63, s = tid >> 6;    // 4 slices
    float acc = 0.f;
    for (int n = lo + s; n < hi; n += 4) acc += g_acc[n * HCD + c];
    __shared__ float sh[256];
    sh[tid] = acc;
    __syncthreads();
    if (s == 0) {
        float v = sh[c] + sh[c + 64] + sh[c + 128] + sh[c + 192];
        float cnt = (float)(hi - lo);
        out[g * HCD + c] = v / fmaxf(cnt, 1.f);
    }
}

// ---------------- launch -----------------------------------------------------
extern "C" void kernel_launch(void* const* d_in, const int* in_sizes, int n_in,
                              void* d_out, int out_size) {
    const float* x   = (const float*)d_in[0];
    const int*   ei  = (const int*)  d_in[1];
    const float* ea  = (const float*)d_in[2];
    const int*   bat = (const int*)  d_in[3];
    const float* W1  = (const float*)d_in[4];
    const float* We1 = (const float*)d_in[5];
    const float* as1 = (const float*)d_in[6];
    const float* ad1 = (const float*)d_in[7];
    const float* ae1 = (const float*)d_in[8];
    const float* b1  = (const float*)d_in[9];
    const float* W2  = (const float*)d_in[10];
    const float* We2 = (const float*)d_in[11];
    const float* as2 = (const float*)d_in[12];
    const float* ad2 = (const float*)d_in[13];
    const float* ae2 = (const float*)d_in[14];
    const float* b2  = (const float*)d_in[15];
    float* out = (float*)d_out;

    const int E4B = (NE / 4 + 255) / 256;          // 782 (4 edges/thread)
    const int NB  = (NN + 255) / 256;              // 196
    const int FB  = (NN * 32 + 255) / 256;         // 6250 (one warp per node)
    const int LB  = (NN + 127) / 128;              // 391 linear tiles

    float *p_h1, *p_acc;
    cudaGetSymbolAddress((void**)&p_h1,  g_h1);
    cudaGetSymbolAddress((void**)&p_acc, g_acc);

    // ---- CSR build (graph static across layers) ----
    k_init<<<NB, 256>>>(We1, ae1, We2, ae2);
    k_hist<<<E4B, 256>>>(ei);
    k_scanA<<<NTILES, 1024>>>();
    k_scanC<<<NTILES, 1024>>>();
    k_scatter<<<E4B, 256>>>(ei, ea);

    // ---- layer 1 ----
    k_linear<128><<<LB, 256>>>(x, W1, as1, ad1);
    k_edge_fused<<<FB, 256>>>(0, b1, p_h1, 1);

    // ---- layer 2 ----
    k_linear<64><<<LB, 256>>>(nullptr, W2, as2, ad2);
    k_edge_fused<<<FB, 256>>>(1, b2, p_acc, 0);

    // ---- pool ----
    k_pool<<<64, 256>>>(bat, out);
}

// round 10
// speedup vs baseline: 1.9339x; 1.0483x over previous
#include <cuda_runtime.h>

#define NN 50000
#define NE 800000
#define HCD 64
#define NTILES 49   // ceil(50000/1024)

// ---------------- scratch (static device globals; allocation-free) ----------
__device__ __align__(16) float g_xs[NN * HCD];      // xs of current layer
__device__ __align__(16) float g_h1[NN * HCD];      // relu(layer1 out)
__device__ __align__(16) float g_acc[NN * HCD];     // layer2 out (pre-pool)
__device__ __align__(16) float g_asrc[NN * 4];      // per-node a_src (4 heads)
__device__ __align__(16) float g_adst[NN * 4];      // per-node a_dst
__device__ __align__(16) float g_ce[8];             // [0..3] layer1, [4..7] layer2
// CSR build
__device__ int g_deg[NN];
__device__ int g_start[NN + 1];
__device__ int g_cursor[NN];
__device__ int g_bsum[NTILES];
__device__ __align__(16) int2 g_edge[NE];           // {src, ea bits} in CSR order

// ---------------- helpers ----------------------------------------------------
__device__ __forceinline__ float red16(float v) {
    v += __shfl_xor_sync(0xffffffffu, v, 8);
    v += __shfl_xor_sync(0xffffffffu, v, 4);
    v += __shfl_xor_sync(0xffffffffu, v, 2);
    v += __shfl_xor_sync(0xffffffffu, v, 1);
    return v;
}

// ---------------- hist (8 edges/thread) + fused ce constants -----------------
__global__ void k_hist(const int* __restrict__ ei,
                       const float* __restrict__ We1, const float* __restrict__ ae1,
                       const float* __restrict__ We2, const float* __restrict__ ae2) {
    if (blockIdx.x == 0 && threadIdx.x < 128) {
        int t = threadIdx.x;
        int layer = t >> 6;
        int c = t & 63;
        const float* We = layer ? We2 : We1;
        const float* ae = layer ? ae2 : ae1;
        float v = red16(We[c] * ae[c]);
        if ((c & 15) == 0) g_ce[layer * 4 + (c >> 4)] = v;
    }
    int t = blockIdx.x * blockDim.x + threadIdx.x;
    int e = t * 8;
    if (e >= NE) return;
    int4 d0 = *(const int4*)&ei[NE + e];
    int4 d1 = *(const int4*)&ei[NE + e + 4];
    atomicAdd(&g_deg[d0.x], 1); atomicAdd(&g_deg[d0.y], 1);
    atomicAdd(&g_deg[d0.z], 1); atomicAdd(&g_deg[d0.w], 1);
    atomicAdd(&g_deg[d1.x], 1); atomicAdd(&g_deg[d1.y], 1);
    atomicAdd(&g_deg[d1.z], 1); atomicAdd(&g_deg[d1.w], 1);
}

// ---------------- scan -------------------------------------------------------
__global__ void k_scanA() {           // per-tile reduction
    __shared__ int wsum[32];
    int b = blockIdx.x, tid = threadIdx.x, lane = tid & 31, w = tid >> 5;
    int i = b * 1024 + tid;
    int v = (i < NN) ? g_deg[i] : 0;
#pragma unroll
    for (int d = 16; d; d >>= 1) v += __shfl_xor_sync(0xffffffffu, v, d);
    if (lane == 0) wsum[w] = v;
    __syncthreads();
    if (w == 0) {
        int t = wsum[lane];
#pragma unroll
        for (int d = 16; d; d >>= 1) t += __shfl_xor_sync(0xffffffffu, t, d);
        if (lane == 0) g_bsum[b] = t;
    }
}

// per-tile scan + (redundant) scan of tile sums for the global offset.
// Cross-warp handoff uses BLOCK-level barriers.
__global__ void k_scanC() {
    __shared__ int wsum[32];
    __shared__ int sboff;
    __shared__ int ws2[2];
    int b = blockIdx.x, tid = threadIdx.x, lane = tid & 31, w = tid >> 5;

    int v2 = 0, x2 = 0;
    if (tid < 64) {
        v2 = (tid < NTILES) ? g_bsum[tid] : 0;
        x2 = v2;
#pragma unroll
        for (int d = 1; d < 32; d <<= 1) {
            int y = __shfl_up_sync(0xffffffffu, x2, d);
            if (lane >= d) x2 += y;
        }
        if (lane == 31) ws2[w] = x2;
    }
    __syncthreads();                       // publish ws2[0] to warp 1
    if (tid >= 32 && tid < 64) x2 += ws2[0];
    if (tid == b) sboff = x2 - v2;         // exclusive offset of this tile
    if (b == 0 && tid == NTILES - 1) g_start[NN] = x2;
    __syncthreads();                       // publish sboff

    int i = b * 1024 + tid;
    int v = (i < NN) ? g_deg[i] : 0;
    int x = v;
#pragma unroll
    for (int d = 1; d < 32; d <<= 1) {
        int y = __shfl_up_sync(0xffffffffu, x, d);
        if (lane >= d) x += y;
    }
    if (lane == 31) wsum[w] = x;
    __syncthreads();
    if (w == 0) {
        int t = wsum[lane];
#pragma unroll
        for (int d = 1; d < 32; d <<= 1) {
            int y = __shfl_up_sync(0xffffffffu, t, d);
            if (lane >= d) t += y;
        }
        wsum[lane] = t;
    }
    __syncthreads();
    int excl = sboff + (w ? wsum[w - 1] : 0) + x - v;
    if (i < NN) { g_start[i] = excl; g_cursor[i] = excl; }
}

// 8 edges per thread, vector loads for MLP.
__global__ void k_scatter(const int* __restrict__ ei, const float* __restrict__ ea) {
    int t = blockIdx.x * blockDim.x + threadIdx.x;
    int e = t * 8;
    if (e >= NE) return;
    int4   s0 = *(const int4*)&ei[e];
    int4   s1 = *(const int4*)&ei[e + 4];
    int4   d0 = *(const int4*)&ei[NE + e];
    int4   d1 = *(const int4*)&ei[NE + e + 4];
    float4 a0 = *(const float4*)&ea[e];
    float4 a1 = *(const float4*)&ea[e + 4];
    int p;
    p = atomicAdd(&g_cursor[d0.x], 1); g_edge[p] = make_int2(s0.x, __float_as_int(a0.x));
    p = atomicAdd(&g_cursor[d0.y], 1); g_edge[p] = make_int2(s0.y, __float_as_int(a0.y));
    p = atomicAdd(&g_cursor[d0.z], 1); g_edge[p] = make_int2(s0.z, __float_as_int(a0.z));
    p = atomicAdd(&g_cursor[d0.w], 1); g_edge[p] = make_int2(s0.w, __float_as_int(a0.w));
    p = atomicAdd(&g_cursor[d1.x], 1); g_edge[p] = make_int2(s1.x, __float_as_int(a1.x));
    p = atomicAdd(&g_cursor[d1.y], 1); g_edge[p] = make_int2(s1.y, __float_as_int(a1.y));
    p = atomicAdd(&g_cursor[d1.z], 1); g_edge[p] = make_int2(s1.z, __float_as_int(a1.z));
    p = atomicAdd(&g_cursor[d1.w], 1); g_edge[p] = make_int2(s1.w, __float_as_int(a1.w));
}

// ---------------- register-blocked linear ------------------------------------
template<int D>
__global__ void __launch_bounds__(256) k_linear(const float* __restrict__ Xext,
                                                const float* __restrict__ W,
                                                const float* __restrict__ as_,
                                                const float* __restrict__ ad_) {
    __shared__ float Wsh[D * 64];
    __shared__ float Xsh[128 * D];
    const float* X = Xext ? Xext : g_h1;
    int tid = threadIdx.x;
    int cg = tid & 7, ng = tid >> 3;
    int c0 = cg * 8;
    int h = cg >> 1;

    for (int i = tid * 4; i < D * 64; i += 1024)
        *(float4*)&Wsh[i] = *(const float4*)&W[i];

    int n0 = blockIdx.x * 128;
    int cnt = NN - n0; if (cnt > 128) cnt = 128;
    for (int i = tid * 4; i < cnt * D; i += 1024)
        *(float4*)&Xsh[i] = *(const float4*)&X[n0 * D + i];
    __syncthreads();

    float acc[4][8];
#pragma unroll
    for (int i = 0; i < 4; i++)
#pragma unroll
        for (int j = 0; j < 8; j++) acc[i][j] = 0.f;

#pragma unroll 2
    for (int k = 0; k < D; k++) {
        float4 wlo = *(const float4*)&Wsh[k * 64 + c0];
        float4 whi = *(const float4*)&Wsh[k * 64 + c0 + 4];
        float wr[8] = {wlo.x, wlo.y, wlo.z, wlo.w, whi.x, whi.y, whi.z, whi.w};
#pragma unroll
        for (int i = 0; i < 4; i++) {
            float xv = Xsh[(ng * 4 + i) * D + k];
#pragma unroll
            for (int j = 0; j < 8; j++)
                acc[i][j] = fmaf(xv, wr[j], acc[i][j]);
        }
    }

    float asv[8], adv[8];
#pragma unroll
    for (int j = 0; j < 8; j++) { asv[j] = as_[c0 + j]; adv[j] = ad_[c0 + j]; }

#pragma unroll
    for (int i = 0; i < 4; i++) {
        int node = n0 + ng * 4 + i;
        float ps = 0.f, pd = 0.f;
#pragma unroll
        for (int j = 0; j < 8; j++) {
            ps = fmaf(acc[i][j], asv[j], ps);
            pd = fmaf(acc[i][j], adv[j], pd);
        }
        ps += __shfl_xor_sync(0xffffffffu, ps, 1);
        pd += __shfl_xor_sync(0xffffffffu, pd, 1);
        if (node < NN) {
            float4 lo = make_float4(acc[i][0], acc[i][1], acc[i][2], acc[i][3]);
            float4 hi = make_float4(acc[i][4], acc[i][5], acc[i][6], acc[i][7]);
            *(float4*)&g_xs[node * HCD + c0] = lo;
            *(float4*)&g_xs[node * HCD + c0 + 4] = hi;
            if ((cg & 1) == 0) {
                g_asrc[node * 4 + h] = ps;
                g_adst[node * 4 + h] = pd;
            }
        }
    }
}

// ---------------- single-pass fused edge aggregation (one warp per dst) ------
// Unrolled x4: batch-load 4 edge records (2x int4), then 4 asrc + 4 xs gathers
// before any dependent math -> MLP ~8 outstanding loads per lane.
__global__ void k_edge_fused(int layer, const float* __restrict__ bias,
                             float* __restrict__ out, int relu) {
    int gw = (blockIdx.x * blockDim.x + threadIdx.x) >> 5;
    if (gw >= NN) return;
    int lane = threadIdx.x & 31;
    int c = lane * 2;               // two consecutive channels, same head
    int h = lane >> 3;
    int s0 = g_start[gw], s1 = g_start[gw + 1];

    float adh = g_adst[gw * 4 + h];
    float cfh = g_ce[layer * 4 + h];

    float acc0 = 0.f, acc1 = 0.f, dsum = 0.f;

    int j = s0;
    // align j to even so int4 loads of g_edge are 16B-aligned
    if (j < s1 && (j & 1)) {
        int2 ep = g_edge[j];
        float sh = g_asrc[ep.x * 4 + h];
        float2 xv = *(const float2*)&g_xs[ep.x * HCD + c];
        float t = sh + adh + cfh * __int_as_float(ep.y);
        t = t > 0.f ? t : 0.2f * t;
        float w = __expf(t);
        dsum += w;
        acc0 = fmaf(w, xv.x, acc0);
        acc1 = fmaf(w, xv.y, acc1);
        ++j;
    }
    for (; j + 3 < s1; j += 4) {
        int4 eA = *(const int4*)&g_edge[j];
        int4 eB = *(const int4*)&g_edge[j + 2];
        int n0i = eA.x, n1i = eA.z, n2i = eB.x, n3i = eB.z;
        // issue all gathers up front
        float sh0 = g_asrc[n0i * 4 + h];
        float sh1 = g_asrc[n1i * 4 + h];
        float sh2 = g_asrc[n2i * 4 + h];
        float sh3 = g_asrc[n3i * 4 + h];
        float2 x0 = *(const float2*)&g_xs[n0i * HCD + c];
        float2 x1 = *(const float2*)&g_xs[n1i * HCD + c];
        float2 x2 = *(const float2*)&g_xs[n2i * HCD + c];
        float2 x3 = *(const float2*)&g_xs[n3i * HCD + c];
        float t0 = sh0 + adh + cfh * __int_as_float(eA.y);
        float t1 = sh1 + adh + cfh * __int_as_float(eA.w);
        float t2 = sh2 + adh + cfh * __int_as_float(eB.y);
        float t3 = sh3 + adh + cfh * __int_as_float(eB.w);
        t0 = t0 > 0.f ? t0 : 0.2f * t0;
        t1 = t1 > 0.f ? t1 : 0.2f * t1;
        t2 = t2 > 0.f ? t2 : 0.2f * t2;
        t3 = t3 > 0.f ? t3 : 0.2f * t3;
        float w0 = __expf(t0), w1 = __expf(t1), w2 = __expf(t2), w3 = __expf(t3);
        dsum += (w0 + w1) + (w2 + w3);
        acc0 = fmaf(w0, x0.x, acc0); acc1 = fmaf(w0, x0.y, acc1);
        acc0 = fmaf(w1, x1.x, acc0); acc1 = fmaf(w1, x1.y, acc1);
        acc0 = fmaf(w2, x2.x, acc0); acc1 = fmaf(w2, x2.y, acc1);
        acc0 = fmaf(w3, x3.x, acc0); acc1 = fmaf(w3, x3.y, acc1);
    }
    for (; j < s1; ++j) {
        int2 ep = g_edge[j];
        float sh = g_asrc[ep.x * 4 + h];
        float2 xv = *(const float2*)&g_xs[ep.x * HCD + c];
        float t = sh + adh + cfh * __int_as_float(ep.y);
        t = t > 0.f ? t : 0.2f * t;
        float w = __expf(t);
        dsum += w;
        acc0 = fmaf(w, xv.x, acc0);
        acc1 = fmaf(w, xv.y, acc1);
    }

    float rcp = (dsum > 0.f) ? (1.f / dsum) : 0.f;
    float2 bv = *(const float2*)&bias[c];
    float o0 = acc0 * rcp + bv.x;
    float o1 = acc1 * rcp + bv.y;
    if (relu) { o0 = fmaxf(o0, 0.f); o1 = fmaxf(o1, 0.f); }
    float2 ov; ov.x = o0; ov.y = o1;
    *(float2*)&out[gw * HCD + c] = ov;
}

// ---------------- pool (batch is sorted -> segment mean per graph) -----------
__device__ __forceinline__ int lowerb(const int* a, int n, int key) {
    int lo = 0, hi = n;
    while (lo < hi) { int m = (lo + hi) >> 1; if (a[m] < key) lo = m + 1; else hi = m; }
    return lo;
}

__global__ void k_pool(const int* __restrict__ batch, float* __restrict__ out) {
    int g = blockIdx.x;
    int lo = lowerb(batch, NN, g);
    int hi = lowerb(batch, NN, g + 1);
    int tid = threadIdx.x;             // 256
    int c = tid & 63, s = tid >> 6;    // 4 slices
    float acc = 0.f;
    for (int n = lo + s; n < hi; n += 4) acc += g_acc[n * HCD + c];
    __shared__ float sh[256];
    sh[tid] = acc;
    __syncthreads();
    if (s == 0) {
        float v = sh[c] + sh[c + 64] + sh[c + 128] + sh[c + 192];
        float cnt = (float)(hi - lo);
        out[g * HCD + c] = v / fmaxf(cnt, 1.f);
    }
}

// ---------------- launch -----------------------------------------------------
extern "C" void kernel_launch(void* const* d_in, const int* in_sizes, int n_in,
                              void* d_out, int out_size) {
    const float* x   = (const float*)d_in[0];
    const int*   ei  = (const int*)  d_in[1];
    const float* ea  = (const float*)d_in[2];
    const int*   bat = (const int*)  d_in[3];
    const float* W1  = (const float*)d_in[4];
    const float* We1 = (const float*)d_in[5];
    const float* as1 = (const float*)d_in[6];
    const float* ad1 = (const float*)d_in[7];
    const float* ae1 = (const float*)d_in[8];
    const float* b1  = (const float*)d_in[9];
    const float* W2  = (const float*)d_in[10];
    const float* We2 = (const float*)d_in[11];
    const float* as2 = (const float*)d_in[12];
    const float* ad2 = (const float*)d_in[13];
    const float* ae2 = (const float*)d_in[14];
    const float* b2  = (const float*)d_in[15];
    float* out = (float*)d_out;

    const int E8B = (NE / 8 + 255) / 256;          // 391 (8 edges/thread)
    const int FB  = (NN * 32 + 255) / 256;         // 6250 (one warp per node)
    const int LB  = (NN + 127) / 128;              // 391 linear tiles

    float *p_h1, *p_acc;
    int *p_deg;
    cudaGetSymbolAddress((void**)&p_h1,  g_h1);
    cudaGetSymbolAddress((void**)&p_acc, g_acc);
    cudaGetSymbolAddress((void**)&p_deg, g_deg);

    // ---- CSR build (graph static across layers) ----
    cudaMemsetAsync(p_deg, 0, NN * sizeof(int));
    k_hist<<<E8B, 256>>>(ei, We1, ae1, We2, ae2);
    k_scanA<<<NTILES, 1024>>>();
    k_scanC<<<NTILES, 1024>>>();
    k_scatter<<<E8B, 256>>>(ei, ea);

    // ---- layer 1 ----
    k_linear<128><<<LB, 256>>>(x, W1, as1, ad1);
    k_edge_fused<<<FB, 256>>>(0, b1, p_h1, 1);

    // ---- layer 2 ----
    k_linear<64><<<LB, 256>>>(nullptr, W2, as2, ad2);
    k_edge_fused<<<FB, 256>>>(1, b2, p_acc, 0);

    // ---- pool ----
    k_pool<<<64, 256>>>(bat, out);
}

// round 11
// speedup vs baseline: 2.1987x; 1.1370x over previous
#include <cuda_runtime.h>

#define NN 50000
#define NE 800000
#define HCD 64
#define NTILES 49   // ceil(50000/1024)

// ---------------- scratch (static device globals; allocation-free) ----------
__device__ __align__(16) float g_xs[NN * HCD];      // xs of current layer
__device__ __align__(16) float g_h1[NN * HCD];      // relu(layer1 out)
__device__ __align__(16) float g_acc[NN * HCD];     // layer2 out (pre-pool)
__device__ __align__(16) float g_asrc[NN * 4];      // per-node a_src (4 heads)
__device__ __align__(16) float g_adst[NN * 4];      // per-node a_dst
__device__ __align__(16) float g_ce[8];             // [0..3] layer1, [4..7] layer2
// CSR build
__device__ int g_deg[NN];
__device__ int g_start[NN + 1];
__device__ int g_cursor[NN];
__device__ int g_bsum[NTILES];
__device__ __align__(16) int2 g_edge[NE];           // {src, ea bits} in CSR order

// ---------------- helpers ----------------------------------------------------
__device__ __forceinline__ float red16(float v) {
    v += __shfl_xor_sync(0xffffffffu, v, 8);
    v += __shfl_xor_sync(0xffffffffu, v, 4);
    v += __shfl_xor_sync(0xffffffffu, v, 2);
    v += __shfl_xor_sync(0xffffffffu, v, 1);
    return v;
}

// ---------------- hist (8 edges/thread) + fused ce constants -----------------
__global__ void k_hist(const int* __restrict__ ei,
                       const float* __restrict__ We1, const float* __restrict__ ae1,
                       const float* __restrict__ We2, const float* __restrict__ ae2) {
    if (blockIdx.x == 0 && threadIdx.x < 128) {
        int t = threadIdx.x;
        int layer = t >> 6;
        int c = t & 63;
        const float* We = layer ? We2 : We1;
        const float* ae = layer ? ae2 : ae1;
        float v = red16(We[c] * ae[c]);
        if ((c & 15) == 0) g_ce[layer * 4 + (c >> 4)] = v;
    }
    int t = blockIdx.x * blockDim.x + threadIdx.x;
    int e = t * 8;
    if (e >= NE) return;
    int4 d0 = *(const int4*)&ei[NE + e];
    int4 d1 = *(const int4*)&ei[NE + e + 4];
    atomicAdd(&g_deg[d0.x], 1); atomicAdd(&g_deg[d0.y], 1);
    atomicAdd(&g_deg[d0.z], 1); atomicAdd(&g_deg[d0.w], 1);
    atomicAdd(&g_deg[d1.x], 1); atomicAdd(&g_deg[d1.y], 1);
    atomicAdd(&g_deg[d1.z], 1); atomicAdd(&g_deg[d1.w], 1);
}

// ---------------- scan -------------------------------------------------------
__global__ void k_scanA() {           // per-tile reduction
    __shared__ int wsum[32];
    int b = blockIdx.x, tid = threadIdx.x, lane = tid & 31, w = tid >> 5;
    int i = b * 1024 + tid;
    int v = (i < NN) ? g_deg[i] : 0;
#pragma unroll
    for (int d = 16; d; d >>= 1) v += __shfl_xor_sync(0xffffffffu, v, d);
    if (lane == 0) wsum[w] = v;
    __syncthreads();
    if (w == 0) {
        int t = wsum[lane];
#pragma unroll
        for (int d = 16; d; d >>= 1) t += __shfl_xor_sync(0xffffffffu, t, d);
        if (lane == 0) g_bsum[b] = t;
    }
}

// per-tile scan + (redundant) scan of tile sums for the global offset.
// Cross-warp handoff uses BLOCK-level barriers.
__global__ void k_scanC() {
    __shared__ int wsum[32];
    __shared__ int sboff;
    __shared__ int ws2[2];
    int b = blockIdx.x, tid = threadIdx.x, lane = tid & 31, w = tid >> 5;

    int v2 = 0, x2 = 0;
    if (tid < 64) {
        v2 = (tid < NTILES) ? g_bsum[tid] : 0;
        x2 = v2;
#pragma unroll
        for (int d = 1; d < 32; d <<= 1) {
            int y = __shfl_up_sync(0xffffffffu, x2, d);
            if (lane >= d) x2 += y;
        }
        if (lane == 31) ws2[w] = x2;
    }
    __syncthreads();                       // publish ws2[0] to warp 1
    if (tid >= 32 && tid < 64) x2 += ws2[0];
    if (tid == b) sboff = x2 - v2;         // exclusive offset of this tile
    if (b == 0 && tid == NTILES - 1) g_start[NN] = x2;
    __syncthreads();                       // publish sboff

    int i = b * 1024 + tid;
    int v = (i < NN) ? g_deg[i] : 0;
    int x = v;
#pragma unroll
    for (int d = 1; d < 32; d <<= 1) {
        int y = __shfl_up_sync(0xffffffffu, x, d);
        if (lane >= d) x += y;
    }
    if (lane == 31) wsum[w] = x;
    __syncthreads();
    if (w == 0) {
        int t = wsum[lane];
#pragma unroll
        for (int d = 1; d < 32; d <<= 1) {
            int y = __shfl_up_sync(0xffffffffu, t, d);
            if (lane >= d) t += y;
        }
        wsum[lane] = t;
    }
    __syncthreads();
    int excl = sboff + (w ? wsum[w - 1] : 0) + x - v;
    if (i < NN) { g_start[i] = excl; g_cursor[i] = excl; }
}

// 8 edges per thread, vector loads for MLP.
__global__ void k_scatter(const int* __restrict__ ei, const float* __restrict__ ea) {
    int t = blockIdx.x * blockDim.x + threadIdx.x;
    int e = t * 8;
    if (e >= NE) return;
    int4   s0 = *(const int4*)&ei[e];
    int4   s1 = *(const int4*)&ei[e + 4];
    int4   d0 = *(const int4*)&ei[NE + e];
    int4   d1 = *(const int4*)&ei[NE + e + 4];
    float4 a0 = *(const float4*)&ea[e];
    float4 a1 = *(const float4*)&ea[e + 4];
    int p;
    p = atomicAdd(&g_cursor[d0.x], 1); g_edge[p] = make_int2(s0.x, __float_as_int(a0.x));
    p = atomicAdd(&g_cursor[d0.y], 1); g_edge[p] = make_int2(s0.y, __float_as_int(a0.y));
    p = atomicAdd(&g_cursor[d0.z], 1); g_edge[p] = make_int2(s0.z, __float_as_int(a0.z));
    p = atomicAdd(&g_cursor[d0.w], 1); g_edge[p] = make_int2(s0.w, __float_as_int(a0.w));
    p = atomicAdd(&g_cursor[d1.x], 1); g_edge[p] = make_int2(s1.x, __float_as_int(a1.x));
    p = atomicAdd(&g_cursor[d1.y], 1); g_edge[p] = make_int2(s1.y, __float_as_int(a1.y));
    p = atomicAdd(&g_cursor[d1.z], 1); g_edge[p] = make_int2(s1.z, __float_as_int(a1.z));
    p = atomicAdd(&g_cursor[d1.w], 1); g_edge[p] = make_int2(s1.w, __float_as_int(a1.w));
}

// ---------------- register-blocked linear ------------------------------------
template<int D>
__global__ void __launch_bounds__(256) k_linear(const float* __restrict__ Xext,
                                                const float* __restrict__ W,
                                                const float* __restrict__ as_,
                                                const float* __restrict__ ad_) {
    __shared__ float Wsh[D * 64];
    __shared__ float Xsh[128 * D];
    const float* X = Xext ? Xext : g_h1;
    int tid = threadIdx.x;
    int cg = tid & 7, ng = tid >> 3;
    int c0 = cg * 8;
    int h = cg >> 1;

    for (int i = tid * 4; i < D * 64; i += 1024)
        *(float4*)&Wsh[i] = *(const float4*)&W[i];

    int n0 = blockIdx.x * 128;
    int cnt = NN - n0; if (cnt > 128) cnt = 128;
    for (int i = tid * 4; i < cnt * D; i += 1024)
        *(float4*)&Xsh[i] = *(const float4*)&X[n0 * D + i];
    __syncthreads();

    float acc[4][8];
#pragma unroll
    for (int i = 0; i < 4; i++)
#pragma unroll
        for (int j = 0; j < 8; j++) acc[i][j] = 0.f;

#pragma unroll 2
    for (int k = 0; k < D; k++) {
        float4 wlo = *(const float4*)&Wsh[k * 64 + c0];
        float4 whi = *(const float4*)&Wsh[k * 64 + c0 + 4];
        float wr[8] = {wlo.x, wlo.y, wlo.z, wlo.w, whi.x, whi.y, whi.z, whi.w};
#pragma unroll
        for (int i = 0; i < 4; i++) {
            float xv = Xsh[(ng * 4 + i) * D + k];
#pragma unroll
            for (int j = 0; j < 8; j++)
                acc[i][j] = fmaf(xv, wr[j], acc[i][j]);
        }
    }

    float asv[8], adv[8];
#pragma unroll
    for (int j = 0; j < 8; j++) { asv[j] = as_[c0 + j]; adv[j] = ad_[c0 + j]; }

#pragma unroll
    for (int i = 0; i < 4; i++) {
        int node = n0 + ng * 4 + i;
        float ps = 0.f, pd = 0.f;
#pragma unroll
        for (int j = 0; j < 8; j++) {
            ps = fmaf(acc[i][j], asv[j], ps);
            pd = fmaf(acc[i][j], adv[j], pd);
        }
        ps += __shfl_xor_sync(0xffffffffu, ps, 1);
        pd += __shfl_xor_sync(0xffffffffu, pd, 1);
        if (node < NN) {
            float4 lo = make_float4(acc[i][0], acc[i][1], acc[i][2], acc[i][3]);
            float4 hi = make_float4(acc[i][4], acc[i][5], acc[i][6], acc[i][7]);
            *(float4*)&g_xs[node * HCD + c0] = lo;
            *(float4*)&g_xs[node * HCD + c0 + 4] = hi;
            if ((cg & 1) == 0) {
                g_asrc[node * 4 + h] = ps;
                g_adst[node * 4 + h] = pd;
            }
        }
    }
}

// ---------------- single-pass fused edge aggregation (one warp per dst) ------
// Unrolled x4: batch-load 4 edge records (2x int4), then 4 asrc + 4 xs gathers
// before any dependent math -> MLP ~8 outstanding loads per lane.
__global__ void k_edge_fused(int layer, const float* __restrict__ bias,
                             float* __restrict__ out, int relu) {
    int gw = (blockIdx.x * blockDim.x + threadIdx.x) >> 5;
    if (gw >= NN) return;
    int lane = threadIdx.x & 31;
    int c = lane * 2;               // two consecutive channels, same head
    int h = lane >> 3;
    int s0 = g_start[gw], s1 = g_start[gw + 1];

    float adh = g_adst[gw * 4 + h];
    float cfh = g_ce[layer * 4 + h];

    float acc0 = 0.f, acc1 = 0.f, dsum = 0.f;

    int j = s0;
    // align j to even so int4 loads of g_edge are 16B-aligned
    if (j < s1 && (j & 1)) {
        int2 ep = g_edge[j];
        float sh = g_asrc[ep.x * 4 + h];
        float2 xv = *(const float2*)&g_xs[ep.x * HCD + c];
        float t = sh + adh + cfh * __int_as_float(ep.y);
        t = t > 0.f ? t : 0.2f * t;
        float w = __expf(t);
        dsum += w;
        acc0 = fmaf(w, xv.x, acc0);
        acc1 = fmaf(w, xv.y, acc1);
        ++j;
    }
    for (; j + 3 < s1; j += 4) {
        int4 eA = *(const int4*)&g_edge[j];
        int4 eB = *(const int4*)&g_edge[j + 2];
        int n0i = eA.x, n1i = eA.z, n2i = eB.x, n3i = eB.z;
        // issue all gathers up front
        float sh0 = g_asrc[n0i * 4 + h];
        float sh1 = g_asrc[n1i * 4 + h];
        float sh2 = g_asrc[n2i * 4 + h];
        float sh3 = g_asrc[n3i * 4 + h];
        float2 x0 = *(const float2*)&g_xs[n0i * HCD + c];
        float2 x1 = *(const float2*)&g_xs[n1i * HCD + c];
        float2 x2 = *(const float2*)&g_xs[n2i * HCD + c];
        float2 x3 = *(const float2*)&g_xs[n3i * HCD + c];
        float t0 = sh0 + adh + cfh * __int_as_float(eA.y);
        float t1 = sh1 + adh + cfh * __int_as_float(eA.w);
        float t2 = sh2 + adh + cfh * __int_as_float(eB.y);
        float t3 = sh3 + adh + cfh * __int_as_float(eB.w);
        t0 = t0 > 0.f ? t0 : 0.2f * t0;
        t1 = t1 > 0.f ? t1 : 0.2f * t1;
        t2 = t2 > 0.f ? t2 : 0.2f * t2;
        t3 = t3 > 0.f ? t3 : 0.2f * t3;
        float w0 = __expf(t0), w1 = __expf(t1), w2 = __expf(t2), w3 = __expf(t3);
        dsum += (w0 + w1) + (w2 + w3);
        acc0 = fmaf(w0, x0.x, acc0); acc1 = fmaf(w0, x0.y, acc1);
        acc0 = fmaf(w1, x1.x, acc0); acc1 = fmaf(w1, x1.y, acc1);
        acc0 = fmaf(w2, x2.x, acc0); acc1 = fmaf(w2, x2.y, acc1);
        acc0 = fmaf(w3, x3.x, acc0); acc1 = fmaf(w3, x3.y, acc1);
    }
    for (; j < s1; ++j) {
        int2 ep = g_edge[j];
        float sh = g_asrc[ep.x * 4 + h];
        float2 xv = *(const float2*)&g_xs[ep.x * HCD + c];
        float t = sh + adh + cfh * __int_as_float(ep.y);
        t = t > 0.f ? t : 0.2f * t;
        float w = __expf(t);
        dsum += w;
        acc0 = fmaf(w, xv.x, acc0);
        acc1 = fmaf(w, xv.y, acc1);
    }

    float rcp = (dsum > 0.f) ? (1.f / dsum) : 0.f;
    float2 bv = *(const float2*)&bias[c];
    float o0 = acc0 * rcp + bv.x;
    float o1 = acc1 * rcp + bv.y;
    if (relu) { o0 = fmaxf(o0, 0.f); o1 = fmaxf(o1, 0.f); }
    float2 ov; ov.x = o0; ov.y = o1;
    *(float2*)&out[gw * HCD + c] = ov;
}

// ---------------- pool (batch is sorted -> segment mean per graph) -----------
__device__ __forceinline__ int lowerb(const int* a, int n, int key) {
    int lo = 0, hi = n;
    while (lo < hi) { int m = (lo + hi) >> 1; if (a[m] < key) lo = m + 1; else hi = m; }
    return lo;
}

__global__ void k_pool(const int* __restrict__ batch, float* __restrict__ out) {
    int g = blockIdx.x;
    int lo = lowerb(batch, NN, g);
    int hi = lowerb(batch, NN, g + 1);
    int tid = threadIdx.x;             // 256
    int c = tid & 63, s = tid >> 6;    // 4 slices
    float acc = 0.f;
    for (int n = lo + s; n < hi; n += 4) acc += g_acc[n * HCD + c];
    __shared__ float sh[256];
    sh[tid] = acc;
    __syncthreads();
    if (s == 0) {
        float v = sh[c] + sh[c + 64] + sh[c + 128] + sh[c + 192];
        float cnt = (float)(hi - lo);
        out[g * HCD + c] = v / fmaxf(cnt, 1.f);
    }
}

// ---------------- launch -----------------------------------------------------
extern "C" void kernel_launch(void* const* d_in, const int* in_sizes, int n_in,
                              void* d_out, int out_size) {
    const float* x   = (const float*)d_in[0];
    const int*   ei  = (const int*)  d_in[1];
    const float* ea  = (const float*)d_in[2];
    const int*   bat = (const int*)  d_in[3];
    const float* W1  = (const float*)d_in[4];
    const float* We1 = (const float*)d_in[5];
    const float* as1 = (const float*)d_in[6];
    const float* ad1 = (const float*)d_in[7];
    const float* ae1 = (const float*)d_in[8];
    const float* b1  = (const float*)d_in[9];
    const float* W2  = (const float*)d_in[10];
    const float* We2 = (const float*)d_in[11];
    const float* as2 = (const float*)d_in[12];
    const float* ad2 = (const float*)d_in[13];
    const float* ae2 = (const float*)d_in[14];
    const float* b2  = (const float*)d_in[15];
    float* out = (float*)d_out;

    const int E8B = (NE / 8 + 255) / 256;          // 391 (8 edges/thread)
    const int FB  = (NN * 32 + 255) / 256;         // 6250 (one warp per node)
    const int LB  = (NN + 127) / 128;              // 391 linear tiles

    float *p_h1, *p_acc;
    int *p_deg;
    cudaGetSymbolAddress((void**)&p_h1,  g_h1);
    cudaGetSymbolAddress((void**)&p_acc, g_acc);
    cudaGetSymbolAddress((void**)&p_deg, g_deg);

    // Fork a side stream for the CSR build so it overlaps with k_linear<128>.
    // (CSR writes deg/start/cursor/edge/ce; linear writes xs/asrc/adst —
    //  disjoint. edge_fused(0) joins both chains.)
    // Handles are created per call and intentionally not destroyed mid-capture
    // (host-side only; no device memory involved).
    cudaStream_t side = 0;
    cudaEvent_t evFork = 0, evJoin = 0;
    bool forked =
        (cudaStreamCreateWithFlags(&side, cudaStreamNonBlocking) == cudaSuccess) &&
        (cudaEventCreateWithFlags(&evFork, cudaEventDisableTiming) == cudaSuccess) &&
        (cudaEventCreateWithFlags(&evJoin, cudaEventDisableTiming) == cudaSuccess);

    cudaStream_t cs = forked ? side : 0;   // CSR stream

    if (forked) {
        cudaEventRecord(evFork, 0);            // fork point on capture stream
        cudaStreamWaitEvent(side, evFork, 0);
    }

    // ---- CSR build (side stream when forked) ----
    cudaMemsetAsync(p_deg, 0, NN * sizeof(int), cs);
    k_hist<<<E8B, 256, 0, cs>>>(ei, We1, ae1, We2, ae2);
    k_scanA<<<NTILES, 1024, 0, cs>>>();
    k_scanC<<<NTILES, 1024, 0, cs>>>();
    k_scatter<<<E8B, 256, 0, cs>>>(ei, ea);

    // ---- layer 1 linear (main stream, concurrent with CSR) ----
    k_linear<128><<<LB, 256>>>(x, W1, as1, ad1);

    if (forked) {
        cudaEventRecord(evJoin, side);         // join CSR chain back
        cudaStreamWaitEvent(0, evJoin, 0);
    }

    // ---- layer 1 aggregation ----
    k_edge_fused<<<FB, 256>>>(0, b1, p_h1, 1);

    // ---- layer 2 ----
    k_linear<64><<<LB, 256>>>(nullptr, W2, as2, ad2);
    k_edge_fused<<<FB, 256>>>(1, b2, p_acc, 0);

    // ---- pool ----
    k_pool<<<64, 256>>>(bat, out);
}